// round 5
// baseline (speedup 1.0000x reference)
#include <cuda_runtime.h>
#include <cuda_fp16.h>

#define N_NODES 100000
#define DIM     128
#define N_ANCH  4096
#define N_SAMP  512
#define INV_TEMP 10.0f

// Normalized feature table in fp16: 100000 * 128 * 2B = 25.6 MB (fits L2).
__device__ __half g_xn[(size_t)N_NODES * DIM];

// Kernel 1: warp per row -> L2-normalize, store fp16. Also zero the output.
__global__ void normalize_kernel(const float* __restrict__ x, float* __restrict__ out) {
    if (blockIdx.x == 0 && threadIdx.x == 0) out[0] = 0.0f;

    int row = blockIdx.x * (blockDim.x >> 5) + (threadIdx.x >> 5);
    if (row >= N_NODES) return;
    int lane = threadIdx.x & 31;

    float4 v = reinterpret_cast<const float4*>(x + (size_t)row * DIM)[lane];
    float s = v.x * v.x + v.y * v.y + v.z * v.z + v.w * v.w;
    #pragma unroll
    for (int o = 16; o; o >>= 1) s += __shfl_xor_sync(0xffffffffu, s, o);
    float inv = rsqrtf(s);

    __half2 h0 = __floats2half2_rn(v.x * inv, v.y * inv);
    __half2 h1 = __floats2half2_rn(v.z * inv, v.w * inv);
    uint2 u;
    u.x = *reinterpret_cast<unsigned*>(&h0);
    u.y = *reinterpret_cast<unsigned*>(&h1);
    reinterpret_cast<uint2*>(g_xn + (size_t)row * DIM)[lane] = u;
}

// Kernel 2: one block per anchor, 8 warps, 16 samples per warp-batch.
// half2 dot math + packed select-fold reduce: 16 shuffles reduce 16 dots;
// lane ends owning sample sig16 = b4 | b3<<1 | b2<<2 | b1<<3 (2 lanes/sample).
__global__ __launch_bounds__(256) void supcon_kernel(
    const int*   __restrict__ y,
    const int*   __restrict__ anchors,
    const int*   __restrict__ sampled,
    float*       __restrict__ out)
{
    const int a    = blockIdx.x;
    const int lane = threadIdx.x & 31;
    const int warp = threadIdx.x >> 5;
    const int sig16 = ((lane >> 4) & 1)        // b4 -> bit0
                    | (((lane >> 3) & 1) << 1) // b3 -> bit1
                    | (((lane >> 2) & 1) << 2) // b2 -> bit2
                    | (((lane >> 1) & 1) << 3);// b1 -> bit3

    __shared__ float s_num[8], s_den[8], s_cnt[8];

    const int anchor = anchors[a];
    const int ya     = y[anchor];

    // Anchor row kept in half2 (4 dims per lane).
    __half2 av0, av1;
    {
        uint2 u = reinterpret_cast<const uint2*>(g_xn + (size_t)anchor * DIM)[lane];
        av0 = *reinterpret_cast<__half2*>(&u.x);
        av1 = *reinterpret_cast<__half2*>(&u.y);
    }

    float num = 0.0f, den = 0.0f, cnt = 0.0f;

    const int*  samp  = sampled + (size_t)a * N_SAMP;
    const int4* samp4 = reinterpret_cast<const int4*>(samp);

    // 512 samples / (8 warps * 16) = 4 iterations.
    #pragma unroll 1
    for (int it = 0; it < 4; ++it) {
        const int base16 = it * 128 + warp * 16;

        // Warp-uniform indices for the 16 row gathers.
        int idx[16];
        {
            const int4 i0 = samp4[(base16 >> 2) + 0];
            const int4 i1 = samp4[(base16 >> 2) + 1];
            const int4 i2 = samp4[(base16 >> 2) + 2];
            const int4 i3 = samp4[(base16 >> 2) + 3];
            idx[0]=i0.x; idx[1]=i0.y; idx[2]=i0.z; idx[3]=i0.w;
            idx[4]=i1.x; idx[5]=i1.y; idx[6]=i1.z; idx[7]=i1.w;
            idx[8]=i2.x; idx[9]=i2.y; idx[10]=i2.z; idx[11]=i2.w;
            idx[12]=i3.x; idx[13]=i3.y; idx[14]=i3.z; idx[15]=i3.w;
        }

        // Per-lane: the sample this lane will own after the packed reduce.
        const int my_idx = samp[base16 + sig16];
        const int my_y   = y[my_idx];

        // 16 independent 256B fp16 row loads + half2 partial dots.
        float d[16];
        #pragma unroll
        for (int j = 0; j < 16; ++j) {
            uint2 u = reinterpret_cast<const uint2*>(g_xn + (size_t)idx[j] * DIM)[lane];
            __half2 s0 = *reinterpret_cast<__half2*>(&u.x);
            __half2 s1 = *reinterpret_cast<__half2*>(&u.y);
            __half2 p  = __hmul2(av0, s0);
            p = __hfma2(av1, s1, p);
            float2 f = __half22float2(p);
            d[j] = f.x + f.y;
        }

        // Packed select-fold reduce: 16 -> 1 per lane-pair, 16 shuffles.
        float e8[8];
        #pragma unroll
        for (int j = 0; j < 8; ++j) {
            float t = (lane & 16) ? d[2*j] : d[2*j + 1];
            float r = __shfl_xor_sync(0xffffffffu, t, 16);
            e8[j] = ((lane & 16) ? d[2*j + 1] : d[2*j]) + r;
        }
        float f4[4];
        #pragma unroll
        for (int j = 0; j < 4; ++j) {
            float t = (lane & 8) ? e8[2*j] : e8[2*j + 1];
            float r = __shfl_xor_sync(0xffffffffu, t, 8);
            f4[j] = ((lane & 8) ? e8[2*j + 1] : e8[2*j]) + r;
        }
        float g2[2];
        #pragma unroll
        for (int j = 0; j < 2; ++j) {
            float t = (lane & 4) ? f4[2*j] : f4[2*j + 1];
            float r = __shfl_xor_sync(0xffffffffu, t, 4);
            g2[j] = ((lane & 4) ? f4[2*j + 1] : f4[2*j]) + r;
        }
        float t2 = (lane & 2) ? g2[0] : g2[1];
        float r2 = __shfl_xor_sync(0xffffffffu, t2, 2);
        float h  = ((lane & 2) ? g2[1] : g2[0]) + r2;
        h += __shfl_xor_sync(0xffffffffu, h, 1);
        // h = full dot of sample (base16 + sig16); each sample held by 2 lanes.

        const float e = __expf(h * INV_TEMP);
        const float m = (my_y == ya) ? 1.0f : 0.0f;
        den += e;
        num += m * e;
        cnt += m;
    }

    // Each sample was accumulated by 2 lanes -> scale by 0.5 after reduce.
    #pragma unroll
    for (int o = 16; o; o >>= 1) {
        den += __shfl_xor_sync(0xffffffffu, den, o);
        num += __shfl_xor_sync(0xffffffffu, num, o);
        cnt += __shfl_xor_sync(0xffffffffu, cnt, o);
    }
    if (lane == 0) {
        s_num[warp] = num * 0.5f;
        s_den[warp] = den * 0.5f;
        s_cnt[warp] = cnt * 0.5f;
    }
    __syncthreads();

    if (threadIdx.x == 0) {
        float tn = 0.0f, td = 0.0f, tc = 0.0f;
        #pragma unroll
        for (int w = 0; w < 8; w++) { tn += s_num[w]; td += s_den[w]; tc += s_cnt[w]; }
        float loss = 0.0f;
        if (tc > 0.0f) loss = -logf(tn / td) / tc;
        atomicAdd(out, loss);
    }
}

extern "C" void kernel_launch(void* const* d_in, const int* in_sizes, int n_in,
                              void* d_out, int out_size) {
    const float* x       = (const float*)d_in[0];
    const int*   y       = (const int*)  d_in[1];
    const int*   anchors = (const int*)  d_in[2];
    const int*   sampled = (const int*)  d_in[3];
    float*       out     = (float*)d_out;

    const int wpb = 8;
    const int blocks = (N_NODES + wpb - 1) / wpb;
    normalize_kernel<<<blocks, wpb * 32>>>(x, out);

    supcon_kernel<<<N_ANCH, 256>>>(y, anchors, sampled, out);
}

// round 6
// speedup vs baseline: 1.4771x; 1.4771x over previous
#include <cuda_runtime.h>
#include <cuda_fp16.h>

#define N_NODES 100000
#define DIM     128
#define N_ANCH  4096
#define N_SAMP  512
#define INV_TEMP 10.0f

// Normalized feature table in fp16: 100000 * 128 * 2B = 25.6 MB (fits L2).
__device__ __half g_xn[(size_t)N_NODES * DIM];

// Kernel 1: warp per row -> L2-normalize, store fp16. Also zero the output.
__global__ void normalize_kernel(const float* __restrict__ x, float* __restrict__ out) {
    if (blockIdx.x == 0 && threadIdx.x == 0) out[0] = 0.0f;

    int row = blockIdx.x * (blockDim.x >> 5) + (threadIdx.x >> 5);
    if (row >= N_NODES) return;
    int lane = threadIdx.x & 31;

    float4 v = reinterpret_cast<const float4*>(x + (size_t)row * DIM)[lane];
    float s = v.x * v.x + v.y * v.y + v.z * v.z + v.w * v.w;
    #pragma unroll
    for (int o = 16; o; o >>= 1) s += __shfl_xor_sync(0xffffffffu, s, o);
    float inv = rsqrtf(s);

    __half2 h0 = __floats2half2_rn(v.x * inv, v.y * inv);
    __half2 h1 = __floats2half2_rn(v.z * inv, v.w * inv);
    uint2 u;
    u.x = *reinterpret_cast<unsigned*>(&h0);
    u.y = *reinterpret_cast<unsigned*>(&h1);
    reinterpret_cast<uint2*>(g_xn + (size_t)row * DIM)[lane] = u;
}

// Kernel 2: one block per anchor, 8 warps, 8 samples per warp-batch (R3
// structure, no spills) with half2 dot math (R4 math). Packed select-fold
// reduce: 9 shuffles reduce 8 dots; lane ends owning sample
// sig = b2<<2 | b3<<1 | b4 (4 lanes per sample).
__global__ __launch_bounds__(256) void supcon_kernel(
    const int*   __restrict__ y,
    const int*   __restrict__ anchors,
    const int*   __restrict__ sampled,
    float*       __restrict__ out)
{
    const int a    = blockIdx.x;
    const int lane = threadIdx.x & 31;
    const int warp = threadIdx.x >> 5;
    const int sig  = (((lane >> 2) & 1) << 2) | (((lane >> 3) & 1) << 1) | ((lane >> 4) & 1);

    __shared__ float s_num[8], s_den[8], s_cnt[8];

    const int anchor = anchors[a];
    const int ya     = y[anchor];

    // Anchor row kept in half2 (4 dims per lane).
    __half2 av0, av1;
    {
        uint2 u = reinterpret_cast<const uint2*>(g_xn + (size_t)anchor * DIM)[lane];
        av0 = *reinterpret_cast<__half2*>(&u.x);
        av1 = *reinterpret_cast<__half2*>(&u.y);
    }

    float num = 0.0f, den = 0.0f, cnt = 0.0f;

    const int*  samp  = sampled + (size_t)a * N_SAMP;
    const int4* samp4 = reinterpret_cast<const int4*>(samp);

    // 512 samples / (8 warps * 8) = 8 iterations.
    #pragma unroll 2
    for (int it = 0; it < 8; ++it) {
        const int base8 = it * 64 + warp * 8;

        // Warp-uniform indices for the 8 row gathers.
        const int4 i0 = samp4[(base8 >> 2)];
        const int4 i1 = samp4[(base8 >> 2) + 1];
        int idx[8] = { i0.x, i0.y, i0.z, i0.w, i1.x, i1.y, i1.z, i1.w };

        // Per-lane: the sample this lane will own after the packed reduce.
        const int my_idx = samp[base8 + sig];
        const int my_y   = y[my_idx];

        // 8 independent 256B fp16 row loads + half2 partial dots (4 dims/lane).
        float d[8];
        #pragma unroll
        for (int j = 0; j < 8; ++j) {
            uint2 u = reinterpret_cast<const uint2*>(g_xn + (size_t)idx[j] * DIM)[lane];
            __half2 s0 = *reinterpret_cast<__half2*>(&u.x);
            __half2 s1 = *reinterpret_cast<__half2*>(&u.y);
            __half2 p  = __hmul2(av0, s0);
            p = __hfma2(av1, s1, p);
            d[j] = __half2float(__hadd(__low2half(p), __high2half(p)));
        }

        // Packed select-fold reduce: 9 shuffles, 8 dots -> 1 per lane.
        float e4[4];
        #pragma unroll
        for (int j = 0; j < 4; ++j) {
            float t = (lane & 16) ? d[2*j] : d[2*j + 1];
            float r = __shfl_xor_sync(0xffffffffu, t, 16);
            e4[j] = ((lane & 16) ? d[2*j + 1] : d[2*j]) + r;
        }
        float f2[2];
        #pragma unroll
        for (int j = 0; j < 2; ++j) {
            float t = (lane & 8) ? e4[2*j] : e4[2*j + 1];
            float r = __shfl_xor_sync(0xffffffffu, t, 8);
            f2[j] = ((lane & 8) ? e4[2*j + 1] : e4[2*j]) + r;
        }
        float t = (lane & 4) ? f2[0] : f2[1];
        float r = __shfl_xor_sync(0xffffffffu, t, 4);
        float g = ((lane & 4) ? f2[1] : f2[0]) + r;
        g += __shfl_xor_sync(0xffffffffu, g, 2);
        g += __shfl_xor_sync(0xffffffffu, g, 1);
        // g = full dot of sample (base8 + sig); each sample held by 4 lanes.

        const float e = __expf(g * INV_TEMP);
        const float m = (my_y == ya) ? 1.0f : 0.0f;
        den += e;
        num += m * e;
        cnt += m;
    }

    // Each sample was accumulated by 4 lanes -> scale by 0.25 after reduce.
    #pragma unroll
    for (int o = 16; o; o >>= 1) {
        den += __shfl_xor_sync(0xffffffffu, den, o);
        num += __shfl_xor_sync(0xffffffffu, num, o);
        cnt += __shfl_xor_sync(0xffffffffu, cnt, o);
    }
    if (lane == 0) {
        s_num[warp] = num * 0.25f;
        s_den[warp] = den * 0.25f;
        s_cnt[warp] = cnt * 0.25f;
    }
    __syncthreads();

    if (threadIdx.x == 0) {
        float tn = 0.0f, td = 0.0f, tc = 0.0f;
        #pragma unroll
        for (int w = 0; w < 8; w++) { tn += s_num[w]; td += s_den[w]; tc += s_cnt[w]; }
        float loss = 0.0f;
        if (tc > 0.0f) loss = -logf(tn / td) / tc;
        atomicAdd(out, loss);
    }
}

extern "C" void kernel_launch(void* const* d_in, const int* in_sizes, int n_in,
                              void* d_out, int out_size) {
    const float* x       = (const float*)d_in[0];
    const int*   y       = (const int*)  d_in[1];
    const int*   anchors = (const int*)  d_in[2];
    const int*   sampled = (const int*)  d_in[3];
    float*       out     = (float*)d_out;

    const int wpb = 8;
    const int blocks = (N_NODES + wpb - 1) / wpb;
    normalize_kernel<<<blocks, wpb * 32>>>(x, out);

    supcon_kernel<<<N_ANCH, 256>>>(y, anchors, sampled, out);
}

// round 7
// speedup vs baseline: 1.6513x; 1.1179x over previous
#include <cuda_runtime.h>
#include <cuda_fp16.h>

#define N_NODES 100000
#define DIM     128
#define N_ANCH  4096
#define N_SAMP  512
// sim = dot_int / 127^2 ; arg = sim / TEMP = dot_int * (10 / 16129)
#define EXP_SCALE (10.0f / 16129.0f)

// Normalized feature table quantized to int8, 4 per int32:
// 100000 * 32 int32 = 12.8 MB (fits L2 easily). Row = 128B = 1 L1 wavefront.
__device__ int g_xq[(size_t)N_NODES * (DIM / 4)];

// Kernel 1: warp per row -> L2-normalize, quantize to int8. Zero the output.
__global__ void quantize_kernel(const float* __restrict__ x, float* __restrict__ out) {
    if (blockIdx.x == 0 && threadIdx.x == 0) out[0] = 0.0f;

    int row = blockIdx.x * (blockDim.x >> 5) + (threadIdx.x >> 5);
    if (row >= N_NODES) return;
    int lane = threadIdx.x & 31;

    float4 v = reinterpret_cast<const float4*>(x + (size_t)row * DIM)[lane];
    float s = v.x * v.x + v.y * v.y + v.z * v.z + v.w * v.w;
    #pragma unroll
    for (int o = 16; o; o >>= 1) s += __shfl_xor_sync(0xffffffffu, s, o);
    float inv = rsqrtf(s) * 127.0f;

    int q0 = __float2int_rn(v.x * inv);
    int q1 = __float2int_rn(v.y * inv);
    int q2 = __float2int_rn(v.z * inv);
    int q3 = __float2int_rn(v.w * inv);
    unsigned pack = (unsigned)(q0 & 0xff)
                  | ((unsigned)(q1 & 0xff) << 8)
                  | ((unsigned)(q2 & 0xff) << 16)
                  | ((unsigned)(q3 & 0xff) << 24);
    g_xq[(size_t)row * (DIM / 4) + lane] = (int)pack;
}

// Kernel 2: one block per anchor, 8 warps, 8 samples per warp-batch.
// Per row: LDG.32 + DP4A (int32 partial dot, 4 dims/lane). Packed int
// select-fold reduce: 9 shuffles, 8 dots -> 1 per lane; lane owns sample
// sig = b2<<2 | b3<<1 | b4 (4 lanes per sample, exact int reduction).
__global__ __launch_bounds__(256) void supcon_kernel(
    const int*   __restrict__ y,
    const int*   __restrict__ anchors,
    const int*   __restrict__ sampled,
    float*       __restrict__ out)
{
    const int a    = blockIdx.x;
    const int lane = threadIdx.x & 31;
    const int warp = threadIdx.x >> 5;
    const int sig  = (((lane >> 2) & 1) << 2) | (((lane >> 3) & 1) << 1) | ((lane >> 4) & 1);

    __shared__ float s_num[8], s_den[8], s_cnt[8];

    const int anchor = anchors[a];
    const int ya     = y[anchor];

    // Anchor row: one packed int32 (4 int8 dims) per lane.
    const int a_pack = g_xq[(size_t)anchor * (DIM / 4) + lane];

    float num = 0.0f, den = 0.0f, cnt = 0.0f;

    const int*  samp  = sampled + (size_t)a * N_SAMP;
    const int4* samp4 = reinterpret_cast<const int4*>(samp);

    // 512 samples / (8 warps * 8) = 8 iterations.
    #pragma unroll 2
    for (int it = 0; it < 8; ++it) {
        const int base8 = it * 64 + warp * 8;

        // Warp-uniform indices for the 8 row gathers.
        const int4 i0 = samp4[(base8 >> 2)];
        const int4 i1 = samp4[(base8 >> 2) + 1];
        int idx[8] = { i0.x, i0.y, i0.z, i0.w, i1.x, i1.y, i1.z, i1.w };

        // Per-lane: the sample this lane will own after the packed reduce.
        const int my_idx = samp[base8 + sig];
        const int my_y   = y[my_idx];

        // 8 independent 128B int8 row loads + DP4A partial dots (4 dims/lane).
        int d[8];
        #pragma unroll
        for (int j = 0; j < 8; ++j) {
            int sp = g_xq[(size_t)idx[j] * (DIM / 4) + lane];
            d[j] = __dp4a(a_pack, sp, 0);
        }

        // Packed select-fold reduce (exact int32): 9 shuffles, 8 -> 1 per lane.
        int e4[4];
        #pragma unroll
        for (int j = 0; j < 4; ++j) {
            int t = (lane & 16) ? d[2*j] : d[2*j + 1];
            int r = __shfl_xor_sync(0xffffffffu, t, 16);
            e4[j] = ((lane & 16) ? d[2*j + 1] : d[2*j]) + r;
        }
        int f2[2];
        #pragma unroll
        for (int j = 0; j < 2; ++j) {
            int t = (lane & 8) ? e4[2*j] : e4[2*j + 1];
            int r = __shfl_xor_sync(0xffffffffu, t, 8);
            f2[j] = ((lane & 8) ? e4[2*j + 1] : e4[2*j]) + r;
        }
        int t = (lane & 4) ? f2[0] : f2[1];
        int r = __shfl_xor_sync(0xffffffffu, t, 4);
        int g = ((lane & 4) ? f2[1] : f2[0]) + r;
        g += __shfl_xor_sync(0xffffffffu, g, 2);
        g += __shfl_xor_sync(0xffffffffu, g, 1);
        // g = full int dot of sample (base8 + sig); held by 4 lanes.

        const float e = __expf(__int2float_rn(g) * EXP_SCALE);
        const float m = (my_y == ya) ? 1.0f : 0.0f;
        den += e;
        num += m * e;
        cnt += m;
    }

    // Each sample was accumulated by 4 lanes -> scale by 0.25 after reduce.
    #pragma unroll
    for (int o = 16; o; o >>= 1) {
        den += __shfl_xor_sync(0xffffffffu, den, o);
        num += __shfl_xor_sync(0xffffffffu, num, o);
        cnt += __shfl_xor_sync(0xffffffffu, cnt, o);
    }
    if (lane == 0) {
        s_num[warp] = num * 0.25f;
        s_den[warp] = den * 0.25f;
        s_cnt[warp] = cnt * 0.25f;
    }
    __syncthreads();

    if (threadIdx.x == 0) {
        float tn = 0.0f, td = 0.0f, tc = 0.0f;
        #pragma unroll
        for (int w = 0; w < 8; w++) { tn += s_num[w]; td += s_den[w]; tc += s_cnt[w]; }
        float loss = 0.0f;
        if (tc > 0.0f) loss = -logf(tn / td) / tc;
        atomicAdd(out, loss);
    }
}

extern "C" void kernel_launch(void* const* d_in, const int* in_sizes, int n_in,
                              void* d_out, int out_size) {
    const float* x       = (const float*)d_in[0];
    const int*   y       = (const int*)  d_in[1];
    const int*   anchors = (const int*)  d_in[2];
    const int*   sampled = (const int*)  d_in[3];
    float*       out     = (float*)d_out;

    const int wpb = 8;
    const int blocks = (N_NODES + wpb - 1) / wpb;
    quantize_kernel<<<blocks, wpb * 32>>>(x, out);

    supcon_kernel<<<N_ANCH, 256>>>(y, anchors, sampled, out);
}

// round 8
// speedup vs baseline: 2.0926x; 1.2673x over previous
#include <cuda_runtime.h>
#include <cuda_fp16.h>

#define N_NODES 100000
#define DIM     128
#define N_ANCH  4096
#define N_SAMP  512
// sim = dot_int / 127^2 ; arg = sim / TEMP = dot_int * (10 / 16129)
#define EXP_SCALE (10.0f / 16129.0f)

// Normalized feature table quantized to int8, 4 per int32:
// 100000 * 32 int32 = 12.8 MB (fits L2 easily). Row = 128B.
__device__ int g_xq[(size_t)N_NODES * (DIM / 4)];

// Kernel 1: warp per row -> L2-normalize, quantize to int8. Zero the output.
__global__ void quantize_kernel(const float* __restrict__ x, float* __restrict__ out) {
    if (blockIdx.x == 0 && threadIdx.x == 0) out[0] = 0.0f;

    int row = blockIdx.x * (blockDim.x >> 5) + (threadIdx.x >> 5);
    if (row >= N_NODES) return;
    int lane = threadIdx.x & 31;

    float4 v = reinterpret_cast<const float4*>(x + (size_t)row * DIM)[lane];
    float s = v.x * v.x + v.y * v.y + v.z * v.z + v.w * v.w;
    #pragma unroll
    for (int o = 16; o; o >>= 1) s += __shfl_xor_sync(0xffffffffu, s, o);
    float inv = rsqrtf(s) * 127.0f;

    int q0 = __float2int_rn(v.x * inv);
    int q1 = __float2int_rn(v.y * inv);
    int q2 = __float2int_rn(v.z * inv);
    int q3 = __float2int_rn(v.w * inv);
    unsigned pack = (unsigned)(q0 & 0xff)
                  | ((unsigned)(q1 & 0xff) << 8)
                  | ((unsigned)(q2 & 0xff) << 16)
                  | ((unsigned)(q3 & 0xff) << 24);
    g_xq[(size_t)row * (DIM / 4) + lane] = (int)pack;
}

// Kernel 2: one block per anchor, 8 warps. Row layout: 8 lanes per row
// (int4 = 16B per lane). Each warp-step covers 4 samples with ONE LDG.128;
// dot = 4 DP4A per lane; reduce = 3-shuffle xor-fold within the 8-lane group
// (exact int32). All 8 group lanes end holding their sample's dot.
__global__ __launch_bounds__(256, 6) void supcon_kernel(
    const int*   __restrict__ y,
    const int*   __restrict__ anchors,
    const int*   __restrict__ sampled,
    float*       __restrict__ out)
{
    const int a    = blockIdx.x;
    const int lane = threadIdx.x & 31;
    const int warp = threadIdx.x >> 5;
    const int grp  = lane >> 3;     // group 0..3 (one sample per group per step)
    const int gl   = lane & 7;      // lane within group (16B slice of the row)

    __shared__ float s_num[8], s_den[8], s_cnt[8];

    const int anchor = anchors[a];
    const int ya     = y[anchor];

    const int4* xq4 = reinterpret_cast<const int4*>(g_xq);

    // Anchor slice for this lane's dim range (same across the 4 groups).
    const int4 a4 = xq4[(size_t)anchor * 8 + gl];

    float num = 0.0f, den = 0.0f, cnt = 0.0f;

    const int* samp = sampled + (size_t)a * N_SAMP;

    // 512 samples / (8 warps * 16 per iter) = 4 iterations; 4 steps/iter.
    #pragma unroll 1
    for (int it = 0; it < 4; ++it) {
        const int base16 = it * 128 + warp * 16;

        // Per-lane sample index for each step (group g takes sample s*4+g).
        int idx[4];
        #pragma unroll
        for (int s = 0; s < 4; ++s)
            idx[s] = samp[base16 + s * 4 + grp];

        // 4 row-slice loads in flight: each LDG.128 fetches 4 full rows.
        int4 sv[4];
        #pragma unroll
        for (int s = 0; s < 4; ++s)
            sv[s] = xq4[(size_t)idx[s] * 8 + gl];

        // Labels for the owned samples (8 lanes share each address).
        int ys[4];
        #pragma unroll
        for (int s = 0; s < 4; ++s)
            ys[s] = y[idx[s]];

        #pragma unroll
        for (int s = 0; s < 4; ++s) {
            int d = __dp4a(a4.x, sv[s].x,
                    __dp4a(a4.y, sv[s].y,
                    __dp4a(a4.z, sv[s].z,
                    __dp4a(a4.w, sv[s].w, 0))));
            // xor-fold within the 8-lane group: exact int dot in all 8 lanes.
            d += __shfl_xor_sync(0xffffffffu, d, 4);
            d += __shfl_xor_sync(0xffffffffu, d, 2);
            d += __shfl_xor_sync(0xffffffffu, d, 1);

            const float e = __expf(__int2float_rn(d) * EXP_SCALE);
            const float m = (ys[s] == ya) ? 1.0f : 0.0f;
            den += e;
            num = fmaf(m, e, num);
            cnt += m;
        }
    }

    // Each sample was accumulated by 8 lanes -> scale by 1/8 after reduce.
    #pragma unroll
    for (int o = 16; o; o >>= 1) {
        den += __shfl_xor_sync(0xffffffffu, den, o);
        num += __shfl_xor_sync(0xffffffffu, num, o);
        cnt += __shfl_xor_sync(0xffffffffu, cnt, o);
    }
    if (lane == 0) {
        s_num[warp] = num * 0.125f;
        s_den[warp] = den * 0.125f;
        s_cnt[warp] = cnt * 0.125f;
    }
    __syncthreads();

    if (threadIdx.x == 0) {
        float tn = 0.0f, td = 0.0f, tc = 0.0f;
        #pragma unroll
        for (int w = 0; w < 8; w++) { tn += s_num[w]; td += s_den[w]; tc += s_cnt[w]; }
        float loss = 0.0f;
        if (tc > 0.0f) loss = -logf(tn / td) / tc;
        atomicAdd(out, loss);
    }
}

extern "C" void kernel_launch(void* const* d_in, const int* in_sizes, int n_in,
                              void* d_out, int out_size) {
    const float* x       = (const float*)d_in[0];
    const int*   y       = (const int*)  d_in[1];
    const int*   anchors = (const int*)  d_in[2];
    const int*   sampled = (const int*)  d_in[3];
    float*       out     = (float*)d_out;

    const int wpb = 8;
    const int blocks = (N_NODES + wpb - 1) / wpb;
    quantize_kernel<<<blocks, wpb * 32>>>(x, out);

    supcon_kernel<<<N_ANCH, 256>>>(y, anchors, sampled, out);
}

// round 9
// speedup vs baseline: 2.3312x; 1.1140x over previous
#include <cuda_runtime.h>
#include <cuda_fp16.h>

#define N_NODES 100000
#define DIM     128
#define N_ANCH  4096
#define N_SAMP  512
// sim = dot_int / 127^2 ; arg = sim / TEMP = dot_int * (10 / 16129)
#define EXP_SCALE (10.0f / 16129.0f)

// Normalized feature table quantized to int8, 4 per int32:
// 100000 * 32 int32 = 12.8 MB (fits L2 easily). Row = 128B.
__device__ int g_xq[(size_t)N_NODES * (DIM / 4)];

// Kernel 1: warp per row -> L2-normalize, quantize to int8. Zero the output.
__global__ void quantize_kernel(const float* __restrict__ x, float* __restrict__ out) {
    if (blockIdx.x == 0 && threadIdx.x == 0) out[0] = 0.0f;

    int row = blockIdx.x * (blockDim.x >> 5) + (threadIdx.x >> 5);
    if (row >= N_NODES) return;
    int lane = threadIdx.x & 31;

    float4 v = reinterpret_cast<const float4*>(x + (size_t)row * DIM)[lane];
    float s = v.x * v.x + v.y * v.y + v.z * v.z + v.w * v.w;
    #pragma unroll
    for (int o = 16; o; o >>= 1) s += __shfl_xor_sync(0xffffffffu, s, o);
    float inv = rsqrtf(s) * 127.0f;

    int q0 = __float2int_rn(v.x * inv);
    int q1 = __float2int_rn(v.y * inv);
    int q2 = __float2int_rn(v.z * inv);
    int q3 = __float2int_rn(v.w * inv);
    unsigned pack = (unsigned)(q0 & 0xff)
                  | ((unsigned)(q1 & 0xff) << 8)
                  | ((unsigned)(q2 & 0xff) << 16)
                  | ((unsigned)(q3 & 0xff) << 24);
    g_xq[(size_t)row * (DIM / 4) + lane] = (int)pack;
}

// Kernel 2: one block per anchor, 8 warps, 32 samples per warp-iteration.
// Row layout: 8 lanes per row (int4/lane). 8 LDG.128 fetch 32 rows; 32 DP4A;
// then a packed select-fold over each 8-lane group (7 shuffles) transposes
// the 32 dots so every lane owns ONE distinct sample's exact int dot:
// sig(gl) = b2 | b1<<1 | b0<<2. Epilogue runs once per sample, zero redundancy.
__global__ __launch_bounds__(256, 5) void supcon_kernel(
    const int*   __restrict__ y,
    const int*   __restrict__ anchors,
    const int*   __restrict__ sampled,
    float*       __restrict__ out)
{
    const int a    = blockIdx.x;
    const int lane = threadIdx.x & 31;
    const int warp = threadIdx.x >> 5;
    const int grp  = lane >> 3;     // group 0..3
    const int gl   = lane & 7;      // lane within group (16B slice of the row)
    // Sample-within-group this lane will own after the packed fold.
    const int sig  = (((lane >> 2) & 1)) | (((lane >> 1) & 1) << 1) | ((lane & 1) << 2);

    __shared__ float s_num[8], s_den[8], s_cnt[8];

    const int anchor = anchors[a];
    const int ya     = y[anchor];

    const int4* xq4 = reinterpret_cast<const int4*>(g_xq);
    const int4  a4  = xq4[(size_t)anchor * 8 + gl];

    float num = 0.0f, den = 0.0f, cnt = 0.0f;

    const int* samp = sampled + (size_t)a * N_SAMP;

    // 512 samples / (8 warps * 32) = 2 iterations.
    #pragma unroll 1
    for (int it = 0; it < 2; ++it) {
        const int base32 = it * 256 + warp * 32;

        // 32 sample indices for this warp batch, one per lane (coalesced).
        const int idx_lane = samp[base32 + lane];

        // Two waves of 4 rows: keeps <=4 LDG.128 + d[] live (no spill).
        int d[8];
        #pragma unroll
        for (int h = 0; h < 2; ++h) {
            int rows[4];
            #pragma unroll
            for (int j = 0; j < 4; ++j)
                rows[j] = __shfl_sync(0xffffffffu, idx_lane, (h * 4 + j) * 4 + grp);
            int4 sv[4];
            #pragma unroll
            for (int j = 0; j < 4; ++j)
                sv[j] = xq4[(size_t)rows[j] * 8 + gl];
            #pragma unroll
            for (int j = 0; j < 4; ++j)
                d[h * 4 + j] = __dp4a(a4.x, sv[j].x,
                               __dp4a(a4.y, sv[j].y,
                               __dp4a(a4.z, sv[j].z,
                               __dp4a(a4.w, sv[j].w, 0))));
        }

        // Packed select-fold within each 8-lane group: 7 shuffles, exact int.
        int e4[4];
        #pragma unroll
        for (int j = 0; j < 4; ++j) {
            int t = (gl & 4) ? d[2*j] : d[2*j + 1];
            int r = __shfl_xor_sync(0xffffffffu, t, 4);
            e4[j] = ((gl & 4) ? d[2*j + 1] : d[2*j]) + r;
        }
        int f2[2];
        #pragma unroll
        for (int j = 0; j < 2; ++j) {
            int t = (gl & 2) ? e4[2*j] : e4[2*j + 1];
            int r = __shfl_xor_sync(0xffffffffu, t, 2);
            f2[j] = ((gl & 2) ? e4[2*j + 1] : e4[2*j]) + r;
        }
        int t1 = (gl & 1) ? f2[0] : f2[1];
        int r1 = __shfl_xor_sync(0xffffffffu, t1, 1);
        int g  = ((gl & 1) ? f2[1] : f2[0]) + r1;
        // g = full int dot of sample (base32 + sig*4 + grp); unique per lane.

        const int my_idx = __shfl_sync(0xffffffffu, idx_lane, sig * 4 + grp);
        const int my_y   = y[my_idx];

        const float e = __expf(__int2float_rn(g) * EXP_SCALE);
        den += e;
        if (my_y == ya) { num += e; cnt += 1.0f; }
    }

    // Warp reduce (each sample counted exactly once across the warp).
    #pragma unroll
    for (int o = 16; o; o >>= 1) {
        den += __shfl_xor_sync(0xffffffffu, den, o);
        num += __shfl_xor_sync(0xffffffffu, num, o);
        cnt += __shfl_xor_sync(0xffffffffu, cnt, o);
    }
    if (lane == 0) { s_num[warp] = num; s_den[warp] = den; s_cnt[warp] = cnt; }
    __syncthreads();

    if (threadIdx.x == 0) {
        float tn = 0.0f, td = 0.0f, tc = 0.0f;
        #pragma unroll
        for (int w = 0; w < 8; w++) { tn += s_num[w]; td += s_den[w]; tc += s_cnt[w]; }
        float loss = 0.0f;
        if (tc > 0.0f) loss = -logf(tn / td) / tc;
        atomicAdd(out, loss);
    }
}

extern "C" void kernel_launch(void* const* d_in, const int* in_sizes, int n_in,
                              void* d_out, int out_size) {
    const float* x       = (const float*)d_in[0];
    const int*   y       = (const int*)  d_in[1];
    const int*   anchors = (const int*)  d_in[2];
    const int*   sampled = (const int*)  d_in[3];
    float*       out     = (float*)d_out;

    const int wpb = 8;
    const int blocks = (N_NODES + wpb - 1) / wpb;
    quantize_kernel<<<blocks, wpb * 32>>>(x, out);

    supcon_kernel<<<N_ANCH, 256>>>(y, anchors, sampled, out);
}

// round 10
// speedup vs baseline: 2.3333x; 1.0009x over previous
#include <cuda_runtime.h>
#include <cuda_fp16.h>

#define N_NODES 100000
#define DIM     128
#define N_ANCH  4096
#define N_SAMP  512
// sim = dot_int / 127^2 ; arg = sim / TEMP = dot_int * (10 / 16129)
#define EXP_SCALE (10.0f / 16129.0f)

// Normalized feature table quantized to int8, 4 per int32:
// 100000 * 32 int32 = 12.8 MB (fits L2 easily). Row = 128B.
__device__ int g_xq[(size_t)N_NODES * (DIM / 4)];

// Kernel 1: warp per row -> L2-normalize, quantize to int8. Zero the output.
__global__ void quantize_kernel(const float* __restrict__ x, float* __restrict__ out) {
    if (blockIdx.x == 0 && threadIdx.x == 0) out[0] = 0.0f;

    int row = blockIdx.x * (blockDim.x >> 5) + (threadIdx.x >> 5);
    if (row >= N_NODES) return;
    int lane = threadIdx.x & 31;

    float4 v = reinterpret_cast<const float4*>(x + (size_t)row * DIM)[lane];
    float s = v.x * v.x + v.y * v.y + v.z * v.z + v.w * v.w;
    #pragma unroll
    for (int o = 16; o; o >>= 1) s += __shfl_xor_sync(0xffffffffu, s, o);
    float inv = rsqrtf(s) * 127.0f;

    int q0 = __float2int_rn(v.x * inv);
    int q1 = __float2int_rn(v.y * inv);
    int q2 = __float2int_rn(v.z * inv);
    int q3 = __float2int_rn(v.w * inv);
    unsigned pack = (unsigned)(q0 & 0xff)
                  | ((unsigned)(q1 & 0xff) << 8)
                  | ((unsigned)(q2 & 0xff) << 16)
                  | ((unsigned)(q3 & 0xff) << 24);
    g_xq[(size_t)row * (DIM / 4) + lane] = (int)pack;
}

// Kernel 2: one block per anchor, 8 warps, 32 samples per warp-iteration.
// Latency-optimized: both iterations' indices hoisted, y-labels prefetched
// BEFORE row loads, and all 8 row LDG.128s issued back-to-back (MLP 8).
// Packed select-fold transposes 32 dots so each lane owns one sample's
// exact int dot; epilogue runs once per sample.
__global__ __launch_bounds__(256, 4) void supcon_kernel(
    const int*   __restrict__ y,
    const int*   __restrict__ anchors,
    const int*   __restrict__ sampled,
    float*       __restrict__ out)
{
    const int a    = blockIdx.x;
    const int lane = threadIdx.x & 31;
    const int warp = threadIdx.x >> 5;
    const int grp  = lane >> 3;     // group 0..3
    const int gl   = lane & 7;      // lane within group (16B slice of the row)
    // Sample-within-group this lane will own after the packed fold.
    const int sig  = (((lane >> 2) & 1)) | (((lane >> 1) & 1) << 1) | ((lane & 1) << 2);

    __shared__ float s_num[8], s_den[8], s_cnt[8];

    const int anchor = anchors[a];
    const int ya     = y[anchor];

    const int4* xq4 = reinterpret_cast<const int4*>(g_xq);
    const int4  a4  = xq4[(size_t)anchor * 8 + gl];

    const int* samp = sampled + (size_t)a * N_SAMP;

    // Hoisted: both iterations' sample indices (coalesced) and prefetched
    // labels for the samples this lane will own (hidden under row gathers).
    const int idx_l0 = samp[warp * 32 + lane];
    const int idx_l1 = samp[256 + warp * 32 + lane];
    const int my_y0  = y[__shfl_sync(0xffffffffu, idx_l0, sig * 4 + grp)];
    const int my_y1  = y[__shfl_sync(0xffffffffu, idx_l1, sig * 4 + grp)];

    float num = 0.0f, den = 0.0f, cnt = 0.0f;

    #pragma unroll
    for (int it = 0; it < 2; ++it) {
        const int idx_lane = it ? idx_l1 : idx_l0;
        const int my_y     = it ? my_y1  : my_y0;

        // Row indices for all 8 rows this group covers.
        int rows[8];
        #pragma unroll
        for (int j = 0; j < 8; ++j)
            rows[j] = __shfl_sync(0xffffffffu, idx_lane, j * 4 + grp);

        // All 8 row loads in flight (one L2 round-trip).
        int4 sv[8];
        #pragma unroll
        for (int j = 0; j < 8; ++j)
            sv[j] = xq4[(size_t)rows[j] * 8 + gl];

        int d[8];
        #pragma unroll
        for (int j = 0; j < 8; ++j)
            d[j] = __dp4a(a4.x, sv[j].x,
                   __dp4a(a4.y, sv[j].y,
                   __dp4a(a4.z, sv[j].z,
                   __dp4a(a4.w, sv[j].w, 0))));

        // Packed select-fold within each 8-lane group: 7 shuffles, exact int.
        int e4[4];
        #pragma unroll
        for (int j = 0; j < 4; ++j) {
            int t = (gl & 4) ? d[2*j] : d[2*j + 1];
            int r = __shfl_xor_sync(0xffffffffu, t, 4);
            e4[j] = ((gl & 4) ? d[2*j + 1] : d[2*j]) + r;
        }
        int f2[2];
        #pragma unroll
        for (int j = 0; j < 2; ++j) {
            int t = (gl & 2) ? e4[2*j] : e4[2*j + 1];
            int r = __shfl_xor_sync(0xffffffffu, t, 2);
            f2[j] = ((gl & 2) ? e4[2*j + 1] : e4[2*j]) + r;
        }
        int t1 = (gl & 1) ? f2[0] : f2[1];
        int r1 = __shfl_xor_sync(0xffffffffu, t1, 1);
        int g  = ((gl & 1) ? f2[1] : f2[0]) + r1;
        // g = full int dot of sample (it*256 + warp*32 + sig*4 + grp).

        const float e = __expf(__int2float_rn(g) * EXP_SCALE);
        den += e;
        if (my_y == ya) { num += e; cnt += 1.0f; }
    }

    // Warp reduce (each sample counted exactly once across the warp).
    #pragma unroll
    for (int o = 16; o; o >>= 1) {
        den += __shfl_xor_sync(0xffffffffu, den, o);
        num += __shfl_xor_sync(0xffffffffu, num, o);
        cnt += __shfl_xor_sync(0xffffffffu, cnt, o);
    }
    if (lane == 0) { s_num[warp] = num; s_den[warp] = den; s_cnt[warp] = cnt; }
    __syncthreads();

    if (threadIdx.x == 0) {
        float tn = 0.0f, td = 0.0f, tc = 0.0f;
        #pragma unroll
        for (int w = 0; w < 8; w++) { tn += s_num[w]; td += s_den[w]; tc += s_cnt[w]; }
        float loss = 0.0f;
        if (tc > 0.0f) loss = -logf(tn / td) / tc;
        atomicAdd(out, loss);
    }
}

extern "C" void kernel_launch(void* const* d_in, const int* in_sizes, int n_in,
                              void* d_out, int out_size) {
    const float* x       = (const float*)d_in[0];
    const int*   y       = (const int*)  d_in[1];
    const int*   anchors = (const int*)  d_in[2];
    const int*   sampled = (const int*)  d_in[3];
    float*       out     = (float*)d_out;

    const int wpb = 8;
    const int blocks = (N_NODES + wpb - 1) / wpb;
    quantize_kernel<<<blocks, wpb * 32>>>(x, out);

    supcon_kernel<<<N_ANCH, 256>>>(y, anchors, sampled, out);
}